// round 9
// baseline (speedup 1.0000x reference)
#include <cuda_runtime.h>
#include <math.h>

// Problem constants (match reference)
#define BB   16
#define CC   128
#define LL   16000
#define KK   256
#define SS   3937          // (L - K)/4 + 1
#define NITER 10
#define STEP 0.1f
#define THR  0.5f
#define NJ   4000          // recon phase length: L/4

// Scratch (no allocations allowed -> __device__ globals)
__device__ float g_drive[BB * CC * SS];   // ~32.25 MB
__device__ float g_u[BB * CC * SS];       // ~32.25 MB
__device__ float g_recon[BB * LL];        // 1 MB, single-rounded fp32 recon

__device__ __forceinline__ float hshrink(float u) {
    return (fabsf(u) > THR) ? u : 0.0f;
}

// ---------------------------------------------------------------------------
// k_conv: strided conv (stride 4, K=256), fp32, k-ascending serial FMA chains
// (verified anchor - unchanged since R5). MODE 0: input = x, writes drive and
// u1 = 0.1f*drive. MODE 1: input = g_recon, fused LCA u-update.
// ---------------------------------------------------------------------------
template <int MODE>
__global__ __launch_bounds__(256) void k_conv(const float* __restrict__ xin,
                                              const float* __restrict__ Wg) {
    __shared__ float Ws[32 * KK];    // 32 KB
    __shared__ float xs[768];        // 3 KB

    const int stile = blockIdx.x;    // 0..30
    const int cb    = blockIdx.y;    // 0..3
    const int b     = blockIdx.z;    // 0..15
    const int s0    = stile * 128;
    const int c0    = cb * 32;
    const int tid   = threadIdx.x;

    const float4* Wg4 = (const float4*)(Wg + c0 * KK);
    float4* Ws4 = (float4*)Ws;
    #pragma unroll
    for (int i = tid; i < (32 * KK) / 4; i += 256) Ws4[i] = Wg4[i];

    {
        const float* src = (MODE == 0) ? (xin + b * LL) : (g_recon + b * LL);
        for (int i = tid; i < 768; i += 256) {
            int gt = 4 * s0 + i;
            xs[i] = (gt < LL) ? src[gt] : 0.0f;
        }
    }
    __syncthreads();

    const int lane = tid & 31;
    const int wg   = tid >> 5;

    float acc[4][4];
    #pragma unroll
    for (int i = 0; i < 4; i++)
        #pragma unroll
        for (int j = 0; j < 4; j++) acc[i][j] = 0.0f;

    const float* wrow = Ws + (wg * 4) * KK;

    #pragma unroll 4
    for (int k = 0; k < KK; k += 4) {
        float4 wv0 = *(const float4*)&wrow[0 * KK + k];
        float4 wv1 = *(const float4*)&wrow[1 * KK + k];
        float4 wv2 = *(const float4*)&wrow[2 * KK + k];
        float4 wv3 = *(const float4*)&wrow[3 * KK + k];
        #pragma unroll
        for (int m = 0; m < 4; m++) {
            float4 xv = *(const float4*)&xs[4 * lane + 128 * m + k];
            acc[0][m] += wv0.x * xv.x; acc[0][m] += wv0.y * xv.y;
            acc[0][m] += wv0.z * xv.z; acc[0][m] += wv0.w * xv.w;
            acc[1][m] += wv1.x * xv.x; acc[1][m] += wv1.y * xv.y;
            acc[1][m] += wv1.z * xv.z; acc[1][m] += wv1.w * xv.w;
            acc[2][m] += wv2.x * xv.x; acc[2][m] += wv2.y * xv.y;
            acc[2][m] += wv2.z * xv.z; acc[2][m] += wv2.w * xv.w;
            acc[3][m] += wv3.x * xv.x; acc[3][m] += wv3.y * xv.y;
            acc[3][m] += wv3.z * xv.z; acc[3][m] += wv3.w * xv.w;
        }
    }

    #pragma unroll
    for (int ci = 0; ci < 4; ci++) {
        const int c = c0 + wg * 4 + ci;
        #pragma unroll
        for (int m = 0; m < 4; m++) {
            const int s = s0 + lane + 32 * m;
            if (s < SS) {
                const int idx = (b * CC + c) * SS + s;
                if (MODE == 0) {
                    g_drive[idx] = acc[ci][m];
                    g_u[idx]     = STEP * acc[ci][m];
                } else {
                    float u = g_u[idx];
                    float a = hshrink(u);
                    float t = ((g_drive[idx] - u) - acc[ci][m]) + a;
                    g_u[idx] = fmaf(STEP, t, u);
                }
            }
        }
    }
}

// ---------------------------------------------------------------------------
// k_recon v4: EXACT R5 kernel (256 threads, 1 j/thread, scalar FFMA, 4
// independent accumulator chains, c = 0..127 outer ascending, d = 63..0
// inner) + ONE addition: per-channel all-zero skip flags (exact +0, proven
// bit-exact in R6/R8). f32x2 retired: packing accs halves chain ILP.
// ---------------------------------------------------------------------------
__global__ __launch_bounds__(256) void k_recon(const float* __restrict__ Wg) {
    extern __shared__ float sm[];
    float* Ws = sm;                       // 32*256 floats (32 KB)
    float* As = sm + 32 * KK;             // 32*320 floats (40 KB)
    int* flags = (int*)(sm + 32 * KK + 32 * 320);   // 32 ints

    const int jt  = blockIdx.x;   // 0..15
    const int b   = blockIdx.y;   // 0..15
    const int j0  = jt * 256;
    const int tid = threadIdx.x;  // 0..255
    const int j   = j0 + tid;

    float acc0 = 0.0f, acc1 = 0.0f, acc2 = 0.0f, acc3 = 0.0f;

    for (int cc = 0; cc < 4; cc++) {
        const int c0 = cc * 32;
        __syncthreads();               // previous chunk fully consumed
        if (tid < 32) flags[tid] = 0;
        __syncthreads();

        // W chunk [c0, c0+32)
        const float4* Wg4 = (const float4*)(Wg + c0 * KK);
        float4* Ws4 = (float4*)Ws;
        #pragma unroll
        for (int i = tid; i < (32 * KK) / 4; i += 256) Ws4[i] = Wg4[i];

        // a window: s in [j0-63, j0+257), 320 per channel; set row flags
        for (int i = tid; i < 32 * 320; i += 256) {
            int c  = i / 320;
            int si = i - c * 320;
            int s  = j0 - 63 + si;
            float v = 0.0f;
            if (s >= 0 && s < SS)
                v = hshrink(g_u[(b * CC + c0 + c) * SS + s]);
            As[i] = v;
            if (v != 0.0f) flags[c] = 1;   // benign race, all writers store 1
        }
        __syncthreads();

        for (int c = 0; c < 32; c++) {
            if (!flags[c]) continue;       // all-zero row: exact +0, skip
            const float* arow = As + c * 320 + tid;   // +(63-d) -> a[j-d]
            const float* wrow = Ws + c * KK;
            #pragma unroll 16
            for (int d = 63; d >= 0; d--) {           // kk ascending
                float4 wv = *(const float4*)&wrow[4 * d];
                float a = arow[63 - d];
                acc0 = fmaf(a, wv.x, acc0);
                acc1 = fmaf(a, wv.y, acc1);
                acc2 = fmaf(a, wv.z, acc2);
                acc3 = fmaf(a, wv.w, acc3);
            }
        }
    }

    if (j < NJ) {
        *(float4*)&g_recon[b * LL + 4 * j] = make_float4(acc0, acc1, acc2, acc3);
    }
}

// ---------------------------------------------------------------------------
// k_out: final a = hardshrink(u), vectorized.
// ---------------------------------------------------------------------------
__global__ __launch_bounds__(256) void k_out(float* __restrict__ out) {
    const int n4 = (BB * CC * SS) / 4;   // 2,015,744
    int i = blockIdx.x * blockDim.x + threadIdx.x;
    if (i < n4) {
        float4 u = ((const float4*)g_u)[i];
        float4 r;
        r.x = hshrink(u.x);
        r.y = hshrink(u.y);
        r.z = hshrink(u.z);
        r.w = hshrink(u.w);
        ((float4*)out)[i] = r;
    }
}

extern "C" void kernel_launch(void* const* d_in, const int* in_sizes, int n_in,
                              void* d_out, int out_size) {
    const float* x = (const float*)d_in[0];   // [16,1,16000]
    const float* W = (const float*)d_in[1];   // [128,1,256]
    float* out = (float*)d_out;               // [16,128,3937]

    const int recon_smem = (32 * KK + 32 * 320 + 32) * (int)sizeof(float); // 73856
    cudaFuncSetAttribute(k_recon, cudaFuncAttributeMaxDynamicSharedMemorySize,
                         recon_smem);

    dim3 gconv(31, 4, BB);
    dim3 grecon(16, BB);

    // Iteration 1: u0 = 0 -> a = 0 -> feedback = 0 -> u1 = 0.1f * drive
    k_conv<0><<<gconv, 256>>>(x, W);

    // Iterations 2..10
    for (int it = 1; it < NITER; it++) {
        k_recon<<<grecon, 256, recon_smem>>>(W);
        k_conv<1><<<gconv, 256>>>(x, W);
    }

    // Final spikegram
    const int n4 = (BB * CC * SS) / 4;
    k_out<<<(n4 + 255) / 256, 256>>>(out);
}

// round 10
// speedup vs baseline: 1.0296x; 1.0296x over previous
#include <cuda_runtime.h>
#include <math.h>

// Problem constants (match reference)
#define BB   16
#define CC   128
#define LL   16000
#define KK   256
#define SS   3937          // (L - K)/4 + 1
#define NITER 10
#define STEP 0.1f
#define THR  0.5f
#define NJ   4000          // recon phase length: L/4

// Scratch (no allocations allowed -> __device__ globals)
__device__ float g_drive[BB * CC * SS];   // ~32.25 MB
__device__ float g_u[BB * CC * SS];       // ~32.25 MB
__device__ float g_recon[BB * LL];        // 1 MB, single-rounded fp32 recon

__device__ __forceinline__ float hshrink(float u) {
    return (fabsf(u) > THR) ? u : 0.0f;
}

// ---------------------------------------------------------------------------
// k_conv: strided conv (stride 4, K=256), fp32, k-ascending serial FMA chains
// (verified anchor - unchanged since R5). MODE 0: input = x, writes drive and
// u1 = 0.1f*drive. MODE 1: input = g_recon, fused LCA u-update.
// ---------------------------------------------------------------------------
template <int MODE>
__global__ __launch_bounds__(256) void k_conv(const float* __restrict__ xin,
                                              const float* __restrict__ Wg) {
    __shared__ float Ws[32 * KK];    // 32 KB
    __shared__ float xs[768];        // 3 KB

    const int stile = blockIdx.x;    // 0..30
    const int cb    = blockIdx.y;    // 0..3
    const int b     = blockIdx.z;    // 0..15
    const int s0    = stile * 128;
    const int c0    = cb * 32;
    const int tid   = threadIdx.x;

    const float4* Wg4 = (const float4*)(Wg + c0 * KK);
    float4* Ws4 = (float4*)Ws;
    #pragma unroll
    for (int i = tid; i < (32 * KK) / 4; i += 256) Ws4[i] = Wg4[i];

    {
        const float* src = (MODE == 0) ? (xin + b * LL) : (g_recon + b * LL);
        for (int i = tid; i < 768; i += 256) {
            int gt = 4 * s0 + i;
            xs[i] = (gt < LL) ? src[gt] : 0.0f;
        }
    }
    __syncthreads();

    const int lane = tid & 31;
    const int wg   = tid >> 5;

    float acc[4][4];
    #pragma unroll
    for (int i = 0; i < 4; i++)
        #pragma unroll
        for (int j = 0; j < 4; j++) acc[i][j] = 0.0f;

    const float* wrow = Ws + (wg * 4) * KK;

    #pragma unroll 4
    for (int k = 0; k < KK; k += 4) {
        float4 wv0 = *(const float4*)&wrow[0 * KK + k];
        float4 wv1 = *(const float4*)&wrow[1 * KK + k];
        float4 wv2 = *(const float4*)&wrow[2 * KK + k];
        float4 wv3 = *(const float4*)&wrow[3 * KK + k];
        #pragma unroll
        for (int m = 0; m < 4; m++) {
            float4 xv = *(const float4*)&xs[4 * lane + 128 * m + k];
            acc[0][m] += wv0.x * xv.x; acc[0][m] += wv0.y * xv.y;
            acc[0][m] += wv0.z * xv.z; acc[0][m] += wv0.w * xv.w;
            acc[1][m] += wv1.x * xv.x; acc[1][m] += wv1.y * xv.y;
            acc[1][m] += wv1.z * xv.z; acc[1][m] += wv1.w * xv.w;
            acc[2][m] += wv2.x * xv.x; acc[2][m] += wv2.y * xv.y;
            acc[2][m] += wv2.z * xv.z; acc[2][m] += wv2.w * xv.w;
            acc[3][m] += wv3.x * xv.x; acc[3][m] += wv3.y * xv.y;
            acc[3][m] += wv3.z * xv.z; acc[3][m] += wv3.w * xv.w;
        }
    }

    #pragma unroll
    for (int ci = 0; ci < 4; ci++) {
        const int c = c0 + wg * 4 + ci;
        #pragma unroll
        for (int m = 0; m < 4; m++) {
            const int s = s0 + lane + 32 * m;
            if (s < SS) {
                const int idx = (b * CC + c) * SS + s;
                if (MODE == 0) {
                    g_drive[idx] = acc[ci][m];
                    g_u[idx]     = STEP * acc[ci][m];
                } else {
                    float u = g_u[idx];
                    float a = hshrink(u);
                    float t = ((g_drive[idx] - u) - acc[ci][m]) + a;
                    g_u[idx] = fmaf(STEP, t, u);
                }
            }
        }
    }
}

// ---------------------------------------------------------------------------
// k_recon v5: EXACT R5 kernel (256 threads, 1 j/thread, scalar FFMA, 4
// independent accumulator chains, c = 0..127 outer ascending, d = 63..0
// inner, branch-free inner loops). ONE change vs R5:
// __launch_bounds__(256, 2) grants ptxas up to 128 regs/thread (R5 chose 32,
// an occupancy heuristic that is pointless here: the kernel is grid-limited
// to <=2 CTAs/SM). Extra registers let the 16x-unrolled loop batch many LDS
// in flight, hiding the 29-cycle shared-memory latency.
// Skip flags (R9) and f32x2 accs (R6/R8) retired: both measured slower.
// ---------------------------------------------------------------------------
__global__ __launch_bounds__(256, 2) void k_recon(const float* __restrict__ Wg) {
    extern __shared__ float sm[];
    float* Ws = sm;              // 32*256 floats (32 KB)
    float* As = sm + 32 * KK;    // 32*320 floats (40 KB)

    const int jt  = blockIdx.x;   // 0..15
    const int b   = blockIdx.y;   // 0..15
    const int j0  = jt * 256;
    const int tid = threadIdx.x;  // 0..255
    const int j   = j0 + tid;

    float acc0 = 0.0f, acc1 = 0.0f, acc2 = 0.0f, acc3 = 0.0f;

    for (int cc = 0; cc < 4; cc++) {
        const int c0 = cc * 32;
        __syncthreads();   // previous chunk fully consumed before overwrite

        // W chunk [c0, c0+32)
        const float4* Wg4 = (const float4*)(Wg + c0 * KK);
        float4* Ws4 = (float4*)Ws;
        #pragma unroll
        for (int i = tid; i < (32 * KK) / 4; i += 256) Ws4[i] = Wg4[i];

        // a window: s in [j0-63, j0+257), 320 per channel
        for (int i = tid; i < 32 * 320; i += 256) {
            int c  = i / 320;
            int si = i - c * 320;
            int s  = j0 - 63 + si;
            float v = 0.0f;
            if (s >= 0 && s < SS)
                v = hshrink(g_u[(b * CC + c0 + c) * SS + s]);
            As[i] = v;
        }
        __syncthreads();

        for (int c = 0; c < 32; c++) {
            const float* arow = As + c * 320 + tid;   // +(63-d) -> a[j-d]
            const float* wrow = Ws + c * KK;
            #pragma unroll 16
            for (int d = 63; d >= 0; d--) {           // kk ascending
                float4 wv = *(const float4*)&wrow[4 * d];
                float a = arow[63 - d];
                acc0 = fmaf(a, wv.x, acc0);
                acc1 = fmaf(a, wv.y, acc1);
                acc2 = fmaf(a, wv.z, acc2);
                acc3 = fmaf(a, wv.w, acc3);
            }
        }
    }

    if (j < NJ) {
        *(float4*)&g_recon[b * LL + 4 * j] = make_float4(acc0, acc1, acc2, acc3);
    }
}

// ---------------------------------------------------------------------------
// k_out: final a = hardshrink(u), vectorized.
// ---------------------------------------------------------------------------
__global__ __launch_bounds__(256) void k_out(float* __restrict__ out) {
    const int n4 = (BB * CC * SS) / 4;   // 2,015,744
    int i = blockIdx.x * blockDim.x + threadIdx.x;
    if (i < n4) {
        float4 u = ((const float4*)g_u)[i];
        float4 r;
        r.x = hshrink(u.x);
        r.y = hshrink(u.y);
        r.z = hshrink(u.z);
        r.w = hshrink(u.w);
        ((float4*)out)[i] = r;
    }
}

extern "C" void kernel_launch(void* const* d_in, const int* in_sizes, int n_in,
                              void* d_out, int out_size) {
    const float* x = (const float*)d_in[0];   // [16,1,16000]
    const float* W = (const float*)d_in[1];   // [128,1,256]
    float* out = (float*)d_out;               // [16,128,3937]

    const int recon_smem = (32 * KK + 32 * 320) * (int)sizeof(float); // 73728 B
    cudaFuncSetAttribute(k_recon, cudaFuncAttributeMaxDynamicSharedMemorySize,
                         recon_smem);

    dim3 gconv(31, 4, BB);
    dim3 grecon(16, BB);

    // Iteration 1: u0 = 0 -> a = 0 -> feedback = 0 -> u1 = 0.1f * drive
    k_conv<0><<<gconv, 256>>>(x, W);

    // Iterations 2..10
    for (int it = 1; it < NITER; it++) {
        k_recon<<<grecon, 256, recon_smem>>>(W);
        k_conv<1><<<gconv, 256>>>(x, W);
    }

    // Final spikegram
    const int n4 = (BB * CC * SS) / 4;
    k_out<<<(n4 + 255) / 256, 256>>>(out);
}

// round 11
// speedup vs baseline: 1.0328x; 1.0031x over previous
#include <cuda_runtime.h>
#include <math.h>

// Problem constants (match reference)
#define BB   16
#define CC   128
#define LL   16000
#define KK   256
#define SS   3937          // (L - K)/4 + 1
#define NITER 10
#define STEP 0.1f
#define THR  0.5f
#define NJ   4000          // recon phase length: L/4

// Scratch (no allocations allowed -> __device__ globals)
__device__ float g_drive[BB * CC * SS];   // ~32.25 MB
__device__ float g_u[BB * CC * SS];       // ~32.25 MB
__device__ float g_recon[BB * LL];        // 1 MB, single-rounded fp32 recon

__device__ __forceinline__ float hshrink(float u) {
    return (fabsf(u) > THR) ? u : 0.0f;
}

// ---------------------------------------------------------------------------
// k_conv: strided conv (stride 4, K=256), fp32, k-ascending serial FMA chains
// (verified anchor - unchanged since R5). MODE 0: input = x, writes drive and
// u1 = 0.1f*drive. MODE 1: input = g_recon, fused LCA u-update.
// ---------------------------------------------------------------------------
template <int MODE>
__global__ __launch_bounds__(256) void k_conv(const float* __restrict__ xin,
                                              const float* __restrict__ Wg) {
    __shared__ float Ws[32 * KK];    // 32 KB
    __shared__ float xs[768];        // 3 KB

    const int stile = blockIdx.x;    // 0..30
    const int cb    = blockIdx.y;    // 0..3
    const int b     = blockIdx.z;    // 0..15
    const int s0    = stile * 128;
    const int c0    = cb * 32;
    const int tid   = threadIdx.x;

    const float4* Wg4 = (const float4*)(Wg + c0 * KK);
    float4* Ws4 = (float4*)Ws;
    #pragma unroll
    for (int i = tid; i < (32 * KK) / 4; i += 256) Ws4[i] = Wg4[i];

    {
        const float* src = (MODE == 0) ? (xin + b * LL) : (g_recon + b * LL);
        for (int i = tid; i < 768; i += 256) {
            int gt = 4 * s0 + i;
            xs[i] = (gt < LL) ? src[gt] : 0.0f;
        }
    }
    __syncthreads();

    const int lane = tid & 31;
    const int wg   = tid >> 5;

    float acc[4][4];
    #pragma unroll
    for (int i = 0; i < 4; i++)
        #pragma unroll
        for (int j = 0; j < 4; j++) acc[i][j] = 0.0f;

    const float* wrow = Ws + (wg * 4) * KK;

    #pragma unroll 4
    for (int k = 0; k < KK; k += 4) {
        float4 wv0 = *(const float4*)&wrow[0 * KK + k];
        float4 wv1 = *(const float4*)&wrow[1 * KK + k];
        float4 wv2 = *(const float4*)&wrow[2 * KK + k];
        float4 wv3 = *(const float4*)&wrow[3 * KK + k];
        #pragma unroll
        for (int m = 0; m < 4; m++) {
            float4 xv = *(const float4*)&xs[4 * lane + 128 * m + k];
            acc[0][m] += wv0.x * xv.x; acc[0][m] += wv0.y * xv.y;
            acc[0][m] += wv0.z * xv.z; acc[0][m] += wv0.w * xv.w;
            acc[1][m] += wv1.x * xv.x; acc[1][m] += wv1.y * xv.y;
            acc[1][m] += wv1.z * xv.z; acc[1][m] += wv1.w * xv.w;
            acc[2][m] += wv2.x * xv.x; acc[2][m] += wv2.y * xv.y;
            acc[2][m] += wv2.z * xv.z; acc[2][m] += wv2.w * xv.w;
            acc[3][m] += wv3.x * xv.x; acc[3][m] += wv3.y * xv.y;
            acc[3][m] += wv3.z * xv.z; acc[3][m] += wv3.w * xv.w;
        }
    }

    #pragma unroll
    for (int ci = 0; ci < 4; ci++) {
        const int c = c0 + wg * 4 + ci;
        #pragma unroll
        for (int m = 0; m < 4; m++) {
            const int s = s0 + lane + 32 * m;
            if (s < SS) {
                const int idx = (b * CC + c) * SS + s;
                if (MODE == 0) {
                    g_drive[idx] = acc[ci][m];
                    g_u[idx]     = STEP * acc[ci][m];
                } else {
                    float u = g_u[idx];
                    float a = hshrink(u);
                    float t = ((g_drive[idx] - u) - acc[ci][m]) + a;
                    g_u[idx] = fmaf(STEP, t, u);
                }
            }
        }
    }
}

// ---------------------------------------------------------------------------
// k_recon v6: R5 structure (256 threads, 1 j/thread, 4 scalar acc chains,
// c = 0..127 outer ascending, d = 63..0 inner) with ONE change: the 64-step
// d-loop is manually software-pipelined as 8 batches of 8 with explicit
// double-buffered register prefetch. Batch k+1's 16 LDS issue before batch
// k's 32 FMAs -> every load gets ~48 issue slots of latency cover (>29cyc),
// which ptxas refused to do on its own (R10: regs 32->79, zero delta).
// Per-accumulator FMA order is IDENTICAL (batches and in-batch u both walk
// d descending) -> bit-exact. ~95 live regs; (256,2) caps at 128.
// ---------------------------------------------------------------------------
__global__ __launch_bounds__(256, 2) void k_recon(const float* __restrict__ Wg) {
    extern __shared__ float sm[];
    float* Ws = sm;              // 32*256 floats (32 KB)
    float* As = sm + 32 * KK;    // 32*320 floats (40 KB)

    const int jt  = blockIdx.x;   // 0..15
    const int b   = blockIdx.y;   // 0..15
    const int j0  = jt * 256;
    const int tid = threadIdx.x;  // 0..255
    const int j   = j0 + tid;

    float acc0 = 0.0f, acc1 = 0.0f, acc2 = 0.0f, acc3 = 0.0f;

    for (int cc = 0; cc < 4; cc++) {
        const int c0 = cc * 32;
        __syncthreads();   // previous chunk fully consumed before overwrite

        // W chunk [c0, c0+32)
        const float4* Wg4 = (const float4*)(Wg + c0 * KK);
        float4* Ws4 = (float4*)Ws;
        #pragma unroll
        for (int i = tid; i < (32 * KK) / 4; i += 256) Ws4[i] = Wg4[i];

        // a window: s in [j0-63, j0+257), 320 per channel
        for (int i = tid; i < 32 * 320; i += 256) {
            int c  = i / 320;
            int si = i - c * 320;
            int s  = j0 - 63 + si;
            float v = 0.0f;
            if (s >= 0 && s < SS)
                v = hshrink(g_u[(b * CC + c0 + c) * SS + s]);
            As[i] = v;
        }
        __syncthreads();

        for (int c = 0; c < 32; c++) {
            const float* arow = As + c * 320 + tid;   // arow[t] = a[j - (63-t)]
            const float* wrow = Ws + c * KK;

            // t = 63 - d runs 0..63 ascending == d descending (kk ascending)
            float4 wvb[2][8];
            float  avb[2][8];

            // prologue: batch 0 (t = 0..7)
            #pragma unroll
            for (int u = 0; u < 8; u++) {
                wvb[0][u] = *(const float4*)&wrow[4 * (63 - u)];
                avb[0][u] = arow[u];
            }

            #pragma unroll
            for (int kb = 0; kb < 8; kb++) {
                const int cur = kb & 1;
                const int nxt = cur ^ 1;
                if (kb < 7) {
                    #pragma unroll
                    for (int u = 0; u < 8; u++) {
                        const int t = 8 * (kb + 1) + u;
                        wvb[nxt][u] = *(const float4*)&wrow[4 * (63 - t)];
                        avb[nxt][u] = arow[t];
                    }
                }
                #pragma unroll
                for (int u = 0; u < 8; u++) {
                    const float  a  = avb[cur][u];
                    const float4 wv = wvb[cur][u];
                    acc0 = fmaf(a, wv.x, acc0);
                    acc1 = fmaf(a, wv.y, acc1);
                    acc2 = fmaf(a, wv.z, acc2);
                    acc3 = fmaf(a, wv.w, acc3);
                }
            }
        }
    }

    if (j < NJ) {
        *(float4*)&g_recon[b * LL + 4 * j] = make_float4(acc0, acc1, acc2, acc3);
    }
}

// ---------------------------------------------------------------------------
// k_out: final a = hardshrink(u), vectorized.
// ---------------------------------------------------------------------------
__global__ __launch_bounds__(256) void k_out(float* __restrict__ out) {
    const int n4 = (BB * CC * SS) / 4;   // 2,015,744
    int i = blockIdx.x * blockDim.x + threadIdx.x;
    if (i < n4) {
        float4 u = ((const float4*)g_u)[i];
        float4 r;
        r.x = hshrink(u.x);
        r.y = hshrink(u.y);
        r.z = hshrink(u.z);
        r.w = hshrink(u.w);
        ((float4*)out)[i] = r;
    }
}

extern "C" void kernel_launch(void* const* d_in, const int* in_sizes, int n_in,
                              void* d_out, int out_size) {
    const float* x = (const float*)d_in[0];   // [16,1,16000]
    const float* W = (const float*)d_in[1];   // [128,1,256]
    float* out = (float*)d_out;               // [16,128,3937]

    const int recon_smem = (32 * KK + 32 * 320) * (int)sizeof(float); // 73728 B
    cudaFuncSetAttribute(k_recon, cudaFuncAttributeMaxDynamicSharedMemorySize,
                         recon_smem);

    dim3 gconv(31, 4, BB);
    dim3 grecon(16, BB);

    // Iteration 1: u0 = 0 -> a = 0 -> feedback = 0 -> u1 = 0.1f * drive
    k_conv<0><<<gconv, 256>>>(x, W);

    // Iterations 2..10
    for (int it = 1; it < NITER; it++) {
        k_recon<<<grecon, 256, recon_smem>>>(W);
        k_conv<1><<<gconv, 256>>>(x, W);
    }

    // Final spikegram
    const int n4 = (BB * CC * SS) / 4;
    k_out<<<(n4 + 255) / 256, 256>>>(out);
}